// round 9
// baseline (speedup 1.0000x reference)
#include <cuda_runtime.h>
#include <cuda_bf16.h>
#include <cstdint>

#define BATCH 2048
#define DDIM  128
#define MDIM  256
#define NKEYS 32768
#define NTILE 256                  // keys per CTA tile
#define CTILES (NKEYS / NTILE)     // 128
#define EST_CONST 0.0048957583f    // float32(sqrt(pi/2)/256)

// -------- static device scratch (no allocations allowed) --------
__device__ __align__(16) __nv_bfloat16 g_Ahi[BATCH * MDIM];
__device__ __align__(16) __nv_bfloat16 g_Alo[BATCH * MDIM];
__device__ __align__(16) __nv_bfloat16 g_Kbf[(size_t)NKEYS * MDIM];
__device__ float g_part[(size_t)BATCH * CTILES * 2];

// ---------------- PTX helpers (compute_103-safe) ----------------
__device__ __forceinline__ uint32_t smem_u32(const void* p) {
    uint32_t a;
    asm("{ .reg .u64 t; cvta.to.shared.u64 t, %1; cvt.u32.u64 %0, t; }" : "=r"(a) : "l"(p));
    return a;
}
__device__ __forceinline__ void cpa16(uint32_t dst, const void* src) {
    asm volatile("cp.async.cg.shared.global [%0], [%1], 16;" :: "r"(dst), "l"(src));
}
#define CP_COMMIT() asm volatile("cp.async.commit_group;" ::: "memory")
template <int N> __device__ __forceinline__ void cp_wait() {
    asm volatile("cp.async.wait_group %0;" :: "n"(N) : "memory");
}
__device__ __forceinline__ void ldm_x4(unsigned* r, uint32_t addr) {
    asm volatile("ldmatrix.sync.aligned.m8n8.x4.shared.b16 {%0,%1,%2,%3}, [%4];"
                 : "=r"(r[0]), "=r"(r[1]), "=r"(r[2]), "=r"(r[3]) : "r"(addr));
}
__device__ __forceinline__ void mma16816(float* c, const unsigned* a, const unsigned* b) {
    asm volatile(
        "mma.sync.aligned.m16n8k16.row.col.f32.bf16.bf16.f32 "
        "{%0,%1,%2,%3}, {%4,%5,%6,%7}, {%8,%9}, {%0,%1,%2,%3};\n"
        : "+f"(c[0]), "+f"(c[1]), "+f"(c[2]), "+f"(c[3])
        : "r"(a[0]), "r"(a[1]), "r"(a[2]), "r"(a[3]), "r"(b[0]), "r"(b[1]));
}

// ---------------------------------------------------------------
// K1: fused prologue.
//  bids [0, 8192):    keys fp32(+/-1) -> bf16 (exact), one float4/thread
//  bids [8192, 8448): projection, 8 batch rows per CTA (sketch read 8x less)
// ---------------------------------------------------------------
__global__ void prologue_kernel(const float* __restrict__ keys,
                                const float* __restrict__ query,
                                const float* __restrict__ sketch) {
    if (blockIdx.x < 8192) {   // -------- convert keys --------
        size_t i = (size_t)blockIdx.x * 256 + threadIdx.x;
        float4 v = __ldg((const float4*)keys + i);
        __nv_bfloat162 a = __floats2bfloat162_rn(v.x, v.y);
        __nv_bfloat162 b = __floats2bfloat162_rn(v.z, v.w);
        ((__nv_bfloat162*)g_Kbf)[2 * i]     = a;
        ((__nv_bfloat162*)g_Kbf)[2 * i + 1] = b;
        return;
    }
    // -------- project 8 batch rows --------
    __shared__ float4 qs[8][DDIM / 4];
    const int b0 = (blockIdx.x - 8192) * 8;
    const int t  = threadIdx.x;          // 0..255
    qs[t >> 5][t & 31] = ((const float4*)(query + (size_t)b0 * DDIM))[t];
    __syncthreads();

    const int m = t;                      // 0..255
    const float4* skr = (const float4*)(sketch + (size_t)m * DDIM);
    float acc[8];
#pragma unroll
    for (int b = 0; b < 8; b++) acc[b] = 0.f;
#pragma unroll
    for (int i = 0; i < DDIM / 4; i++) {
        float4 s = skr[i];
#pragma unroll
        for (int b = 0; b < 8; b++) {
            float4 a = qs[b][i];          // smem broadcast (conflict-free)
            acc[b] += a.x * s.x + a.y * s.y + a.z * s.z + a.w * s.w;
        }
    }
#pragma unroll
    for (int b = 0; b < 8; b++) {
        __nv_bfloat16 hi = __float2bfloat16(acc[b]);
        float rem = acc[b] - __bfloat162float(hi);
        g_Ahi[(size_t)(b0 + b) * MDIM + m] = hi;
        g_Alo[(size_t)(b0 + b) * MDIM + m] = __float2bfloat16(rem);
    }
}

// ---------------------------------------------------------------
// K2: HMMA GEMM (R4-proven, unchanged). CTA 128(M) x 256(N),
// K=256 in 8 chunks of 32, hi/lo folded, cp.async double buffer.
// 8 warps, warp tile 64x64. Rows padded to 80B (conflict-free).
// ---------------------------------------------------------------
#define ROWB 80                      // bytes per smem row (32 bf16 + pad)
#define ASZ  (128 * ROWB)            // 10240 B per A operand
#define BSZ  (256 * ROWB)            // 20480 B
#define STAGE (2 * ASZ + BSZ)        // 40960 B
#define SMEM_DYN (2 * STAGE)         // 81920 B

__global__ void __launch_bounds__(256, 1)
gemm_kernel(const float* __restrict__ norms, float* __restrict__ out) {
    extern __shared__ char dsm[];
    __shared__ float  sNorm[NTILE];
    __shared__ float2 sRed[4][128];

    const int tid  = threadIdx.x;
    const int wid  = tid >> 5;
    const int lane = tid & 31;
    const int warp_m = wid & 1;   // 2 over 128 rows (64 each)
    const int warp_n = wid >> 1;  // 4 over 256 cols (64 each)
    const int g = lane >> 2;
    const int q = lane & 3;
    const int row0 = blockIdx.x * 128;
    const int n0   = blockIdx.y * NTILE;

    const uint32_t base = smem_u32(dsm);

    for (int i = tid; i < NTILE; i += 256)
        sNorm[i] = __ldg(norms + n0 + i) * EST_CONST;

    float acc[4][8][4];
#pragma unroll
    for (int mt = 0; mt < 4; mt++)
#pragma unroll
        for (int nt = 0; nt < 8; nt++)
#pragma unroll
            for (int c = 0; c < 4; c++) acc[mt][nt][c] = 0.f;

    const int aRow = warp_m * 64 + (lane & 7) + ((lane >> 3) & 1) * 8;  // + mt*16
    const int aKh  = (lane >> 4) * 16;
    const int bRow = warp_n * 64 + (lane & 7) + ((lane >> 4) & 1) * 8;  // + ntp*16
    const int bKh  = ((lane >> 3) & 1) * 16;

    auto load_chunk = [&](int kc, int buf) {
        const uint32_t sb = base + buf * STAGE;
        const __nv_bfloat16* srcH = g_Ahi + (size_t)row0 * MDIM + kc * 32;
        const __nv_bfloat16* srcL = g_Alo + (size_t)row0 * MDIM + kc * 32;
        const __nv_bfloat16* srcB = g_Kbf + (size_t)n0 * MDIM + kc * 32;
#pragma unroll
        for (int i = 0; i < 2; i++) {            // A hi/lo: 128 rows x 4 segs
            int idx = tid + i * 256;
            int r = idx >> 2, sg = idx & 3;
            uint32_t so = (uint32_t)(r * ROWB + sg * 16);
            cpa16(sb + so,       srcH + (size_t)r * MDIM + sg * 8);
            cpa16(sb + ASZ + so, srcL + (size_t)r * MDIM + sg * 8);
        }
#pragma unroll
        for (int i = 0; i < 4; i++) {            // B: 256 rows x 4 segs
            int idx = tid + i * 256;
            int r = idx >> 2, sg = idx & 3;
            cpa16(sb + 2 * ASZ + (uint32_t)(r * ROWB + sg * 16),
                  srcB + (size_t)r * MDIM + sg * 8);
        }
        CP_COMMIT();
    };

    auto compute = [&](int buf) {
        const uint32_t sb  = base + buf * STAGE;
        const uint32_t aH  = sb;
        const uint32_t aL  = sb + ASZ;
        const uint32_t bB  = sb + 2 * ASZ;
#pragma unroll
        for (int kk = 0; kk < 2; kk++) {
            const int kb = kk * 32;  // 16 bf16 = 32 bytes
            unsigned ah[4][4], al[4][4], bb[8][2];
#pragma unroll
            for (int mt = 0; mt < 4; mt++) {
                uint32_t ao = (uint32_t)((aRow + mt * 16) * ROWB + kb + aKh);
                ldm_x4(ah[mt], aH + ao);
                ldm_x4(al[mt], aL + ao);
            }
#pragma unroll
            for (int ntp = 0; ntp < 4; ntp++) {
                unsigned t[4];
                ldm_x4(t, bB + (uint32_t)((bRow + ntp * 16) * ROWB + kb + bKh));
                bb[2 * ntp][0] = t[0]; bb[2 * ntp][1] = t[1];
                bb[2 * ntp + 1][0] = t[2]; bb[2 * ntp + 1][1] = t[3];
            }
#pragma unroll
            for (int mt = 0; mt < 4; mt++)
#pragma unroll
                for (int nt = 0; nt < 8; nt++) {
                    mma16816(acc[mt][nt], ah[mt], bb[nt]);
                    mma16816(acc[mt][nt], al[mt], bb[nt]);
                }
        }
    };

    // ---- pipeline: 8 chunks, 2-stage ring ----
    load_chunk(0, 0);
#pragma unroll
    for (int kc = 0; kc < 8; kc++) {
        if (kc < 7) {
            load_chunk(kc + 1, (kc + 1) & 1);
            cp_wait<1>();
        } else {
            cp_wait<0>();
        }
        __syncthreads();
        compute(kc & 1);
        __syncthreads();
    }

    // ---- epilogue: scale, write raw scores, (max,sumexp) partials ----
#pragma unroll
    for (int mt = 0; mt < 4; mt++) {
#pragma unroll
        for (int nt = 0; nt < 8; nt++) {
            int cl = warp_n * 64 + nt * 8 + 2 * q;
            float s0 = sNorm[cl];
            float s1 = sNorm[cl + 1];
            acc[mt][nt][0] *= s0;
            acc[mt][nt][1] *= s1;
            acc[mt][nt][2] *= s0;
            acc[mt][nt][3] *= s1;
        }
#pragma unroll
        for (int h = 0; h < 2; h++) {
            int rloc = warp_m * 64 + mt * 16 + g + h * 8;
            size_t orow = (size_t)(row0 + rloc) * NKEYS + n0;
            float mymax = -3.0e38f;
#pragma unroll
            for (int nt = 0; nt < 8; nt++) {
                int cl = warp_n * 64 + nt * 8 + 2 * q;
                float v0 = acc[mt][nt][h * 2 + 0];
                float v1 = acc[mt][nt][h * 2 + 1];
                *reinterpret_cast<float2*>(out + orow + cl) = make_float2(v0, v1);
                mymax = fmaxf(mymax, fmaxf(v0, v1));
            }
            float s = 0.f;
#pragma unroll
            for (int nt = 0; nt < 8; nt++) {
                s += __expf(acc[mt][nt][h * 2 + 0] - mymax);
                s += __expf(acc[mt][nt][h * 2 + 1] - mymax);
            }
#pragma unroll
            for (int off = 1; off <= 2; off <<= 1) {
                float mo = __shfl_xor_sync(0xffffffffu, mymax, off);
                float so = __shfl_xor_sync(0xffffffffu, s, off);
                float nm = fmaxf(mymax, mo);
                s = s * __expf(mymax - nm) + so * __expf(mo - nm);
                mymax = nm;
            }
            if (q == 0) sRed[warp_n][rloc] = make_float2(mymax, s);
        }
    }
    __syncthreads();
    if (tid < 128) {
        float2 a = sRed[0][tid], b = sRed[1][tid];
        float2 c = sRed[2][tid], d = sRed[3][tid];
        float M = fmaxf(fmaxf(a.x, b.x), fmaxf(c.x, d.x));
        float S = a.y * __expf(a.x - M) + b.y * __expf(b.x - M) +
                  c.y * __expf(c.x - M) + d.y * __expf(d.x - M);
        size_t p = ((size_t)(row0 + tid) * CTILES + blockIdx.y) * 2;
        g_part[p]     = M;
        g_part[p + 1] = S;
    }
}

// ---------------------------------------------------------------
// K3: fused reduce + normalize.
// grid = BATCH*8; CTA handles row = bid>>3, col chunk = (bid&7)*4096.
// First re-derives (M, 1/S) from the row's 128 partials (2KB, L2-hot),
// then normalizes its 4096 columns with streaming loads/stores.
// ---------------------------------------------------------------
__global__ void __launch_bounds__(256)
norm_kernel(float* __restrict__ out) {
    __shared__ float sm[4], ss[4];
    __shared__ float2 sStat;
    const int row   = blockIdx.x >> 3;
    const int chunk = blockIdx.x & 7;
    const int t     = threadIdx.x;

    // ---- per-row stats from partials ----
    if (t < 128) {
        float2 x = ((const float2*)g_part)[(size_t)row * CTILES + t];
        float m = x.x, s = x.y;
#pragma unroll
        for (int off = 16; off; off >>= 1) {
            float mo = __shfl_xor_sync(0xffffffffu, m, off);
            float so = __shfl_xor_sync(0xffffffffu, s, off);
            float nm = fmaxf(m, mo);
            s = s * __expf(m - nm) + so * __expf(mo - nm);
            m = nm;
        }
        if ((t & 31) == 0) { sm[t >> 5] = m; ss[t >> 5] = s; }
    }
    __syncthreads();
    if (t == 0) {
        float m = sm[0], s = ss[0];
#pragma unroll
        for (int i = 1; i < 4; i++) {
            float nm = fmaxf(m, sm[i]);
            s = s * __expf(m - nm) + ss[i] * __expf(sm[i] - nm);
            m = nm;
        }
        sStat = make_float2(m, 1.0f / s);
    }
    __syncthreads();
    const float M = sStat.x, invS = sStat.y;

    // ---- normalize 4096 columns (1024 float4, 4 independent per thread) ----
    float4* p = (float4*)(out + (size_t)row * NKEYS + chunk * 4096);
    float4 v0 = __ldcs(p + t);
    float4 v1 = __ldcs(p + t + 256);
    float4 v2 = __ldcs(p + t + 512);
    float4 v3 = __ldcs(p + t + 768);
    v0.x = __expf(v0.x - M) * invS; v0.y = __expf(v0.y - M) * invS;
    v0.z = __expf(v0.z - M) * invS; v0.w = __expf(v0.w - M) * invS;
    v1.x = __expf(v1.x - M) * invS; v1.y = __expf(v1.y - M) * invS;
    v1.z = __expf(v1.z - M) * invS; v1.w = __expf(v1.w - M) * invS;
    v2.x = __expf(v2.x - M) * invS; v2.y = __expf(v2.y - M) * invS;
    v2.z = __expf(v2.z - M) * invS; v2.w = __expf(v2.w - M) * invS;
    v3.x = __expf(v3.x - M) * invS; v3.y = __expf(v3.y - M) * invS;
    v3.z = __expf(v3.z - M) * invS; v3.w = __expf(v3.w - M) * invS;
    __stcs(p + t,       v0);
    __stcs(p + t + 256, v1);
    __stcs(p + t + 512, v2);
    __stcs(p + t + 768, v3);
}

// ---------------------------------------------------------------
extern "C" void kernel_launch(void* const* d_in, const int* in_sizes, int n_in,
                              void* d_out, int out_size) {
    const float* query  = (const float*)d_in[0];  // [2048, 128]
    const float* keys   = (const float*)d_in[1];  // [32768, 256] (+/-1)
    const float* norms  = (const float*)d_in[2];  // [32768]
    const float* sketch = (const float*)d_in[3];  // [256, 128]
    float* out = (float*)d_out;                   // [2048, 32768]

    cudaFuncSetAttribute(gemm_kernel, cudaFuncAttributeMaxDynamicSharedMemorySize, SMEM_DYN);

    prologue_kernel<<<8192 + BATCH / 8, 256>>>(keys, query, sketch);
    dim3 g2(BATCH / 128, CTILES);  // m-fastest: slabs share key tiles in-wave
    gemm_kernel<<<g2, 256, SMEM_DYN>>>(norms, out);
    norm_kernel<<<BATCH * 8, 256>>>(out);
}

// round 10
// speedup vs baseline: 1.4456x; 1.4456x over previous
#include <cuda_runtime.h>
#include <cuda_bf16.h>
#include <cstdint>

#define BATCH 2048
#define DDIM  128
#define MDIM  256
#define NKEYS 32768
#define NTILE 256                  // keys per CTA tile
#define CTILES (NKEYS / NTILE)     // 128
#define EST_CONST 0.0048957583f    // float32(sqrt(pi/2)/256)

// -------- static device scratch (no allocations allowed) --------
__device__ __align__(16) __nv_bfloat16 g_Ahi[BATCH * MDIM];
__device__ __align__(16) __nv_bfloat16 g_Alo[BATCH * MDIM];
__device__ __align__(16) __nv_bfloat16 g_Kbf[(size_t)NKEYS * MDIM];
__device__ float  g_part[(size_t)BATCH * CTILES * 2];
__device__ float2 g_rowstats[BATCH];

// ---------------- PTX helpers (compute_103-safe) ----------------
__device__ __forceinline__ uint32_t smem_u32(const void* p) {
    uint32_t a;
    asm("{ .reg .u64 t; cvta.to.shared.u64 t, %1; cvt.u32.u64 %0, t; }" : "=r"(a) : "l"(p));
    return a;
}
__device__ __forceinline__ void cpa16(uint32_t dst, const void* src) {
    asm volatile("cp.async.cg.shared.global [%0], [%1], 16;" :: "r"(dst), "l"(src));
}
#define CP_COMMIT() asm volatile("cp.async.commit_group;" ::: "memory")
template <int N> __device__ __forceinline__ void cp_wait() {
    asm volatile("cp.async.wait_group %0;" :: "n"(N) : "memory");
}
__device__ __forceinline__ void ldm_x4(unsigned* r, uint32_t addr) {
    asm volatile("ldmatrix.sync.aligned.m8n8.x4.shared.b16 {%0,%1,%2,%3}, [%4];"
                 : "=r"(r[0]), "=r"(r[1]), "=r"(r[2]), "=r"(r[3]) : "r"(addr));
}
__device__ __forceinline__ void mma16816(float* c, const unsigned* a, const unsigned* b) {
    asm volatile(
        "mma.sync.aligned.m16n8k16.row.col.f32.bf16.bf16.f32 "
        "{%0,%1,%2,%3}, {%4,%5,%6,%7}, {%8,%9}, {%0,%1,%2,%3};\n"
        : "+f"(c[0]), "+f"(c[1]), "+f"(c[2]), "+f"(c[3])
        : "r"(a[0]), "r"(a[1]), "r"(a[2]), "r"(a[3]), "r"(b[0]), "r"(b[1]));
}

// ---------------------------------------------------------------
// K0: convert keys fp32 (+/-1) -> bf16 (exact). Standalone: low regs,
// full occupancy. __ldcs: single-use fp32 stream must not evict the
// bf16 key image from L2.
// ---------------------------------------------------------------
__global__ void convert_keys(const float* __restrict__ keys) {
    size_t i = (size_t)blockIdx.x * blockDim.x + threadIdx.x;  // one float4 each
    float4 v = __ldcs((const float4*)keys + i);
    __nv_bfloat162 a = __floats2bfloat162_rn(v.x, v.y);
    __nv_bfloat162 b = __floats2bfloat162_rn(v.z, v.w);
    ((__nv_bfloat162*)g_Kbf)[2 * i]     = a;
    ((__nv_bfloat162*)g_Kbf)[2 * i + 1] = b;
}

// ---------------------------------------------------------------
// K1: projection, 8 batch rows per CTA (sketch traffic 8x lower than
// one-row-per-CTA). PQ = query @ sketch^T -> bf16 hi/lo split.
// ---------------------------------------------------------------
__global__ void project_kernel(const float* __restrict__ query,
                               const float* __restrict__ sketch) {
    __shared__ float4 qs[8][DDIM / 4];
    const int b0 = blockIdx.x * 8;
    const int t  = threadIdx.x;          // 0..255
    qs[t >> 5][t & 31] = ((const float4*)(query + (size_t)b0 * DDIM))[t];
    __syncthreads();

    const int m = t;                      // 0..255
    const float4* skr = (const float4*)(sketch + (size_t)m * DDIM);
    float acc[8];
#pragma unroll
    for (int b = 0; b < 8; b++) acc[b] = 0.f;
#pragma unroll
    for (int i = 0; i < DDIM / 4; i++) {
        float4 s = skr[i];
#pragma unroll
        for (int b = 0; b < 8; b++) {
            float4 a = qs[b][i];          // smem broadcast (conflict-free)
            acc[b] += a.x * s.x + a.y * s.y + a.z * s.z + a.w * s.w;
        }
    }
#pragma unroll
    for (int b = 0; b < 8; b++) {
        __nv_bfloat16 hi = __float2bfloat16(acc[b]);
        float rem = acc[b] - __bfloat162float(hi);
        g_Ahi[(size_t)(b0 + b) * MDIM + m] = hi;
        g_Alo[(size_t)(b0 + b) * MDIM + m] = __float2bfloat16(rem);
    }
}

// ---------------------------------------------------------------
// K2: HMMA GEMM (R4-proven, verbatim). CTA 128(M) x 256(N),
// K=256 in 8 chunks of 32, hi/lo folded, cp.async double buffer.
// 8 warps, warp tile 64x64. Rows padded to 80B (conflict-free).
// ---------------------------------------------------------------
#define ROWB 80                      // bytes per smem row (32 bf16 + pad)
#define ASZ  (128 * ROWB)            // 10240 B per A operand
#define BSZ  (256 * ROWB)            // 20480 B
#define STAGE (2 * ASZ + BSZ)        // 40960 B
#define SMEM_DYN (2 * STAGE)         // 81920 B

__global__ void __launch_bounds__(256, 1)
gemm_kernel(const float* __restrict__ norms, float* __restrict__ out) {
    extern __shared__ char dsm[];
    __shared__ float  sNorm[NTILE];
    __shared__ float2 sRed[4][128];

    const int tid  = threadIdx.x;
    const int wid  = tid >> 5;
    const int lane = tid & 31;
    const int warp_m = wid & 1;   // 2 over 128 rows (64 each)
    const int warp_n = wid >> 1;  // 4 over 256 cols (64 each)
    const int g = lane >> 2;
    const int q = lane & 3;
    const int row0 = blockIdx.x * 128;
    const int n0   = blockIdx.y * NTILE;

    const uint32_t base = smem_u32(dsm);

    for (int i = tid; i < NTILE; i += 256)
        sNorm[i] = __ldg(norms + n0 + i) * EST_CONST;

    float acc[4][8][4];
#pragma unroll
    for (int mt = 0; mt < 4; mt++)
#pragma unroll
        for (int nt = 0; nt < 8; nt++)
#pragma unroll
            for (int c = 0; c < 4; c++) acc[mt][nt][c] = 0.f;

    const int aRow = warp_m * 64 + (lane & 7) + ((lane >> 3) & 1) * 8;  // + mt*16
    const int aKh  = (lane >> 4) * 16;
    const int bRow = warp_n * 64 + (lane & 7) + ((lane >> 4) & 1) * 8;  // + ntp*16
    const int bKh  = ((lane >> 3) & 1) * 16;

    auto load_chunk = [&](int kc, int buf) {
        const uint32_t sb = base + buf * STAGE;
        const __nv_bfloat16* srcH = g_Ahi + (size_t)row0 * MDIM + kc * 32;
        const __nv_bfloat16* srcL = g_Alo + (size_t)row0 * MDIM + kc * 32;
        const __nv_bfloat16* srcB = g_Kbf + (size_t)n0 * MDIM + kc * 32;
#pragma unroll
        for (int i = 0; i < 2; i++) {            // A hi/lo: 128 rows x 4 segs
            int idx = tid + i * 256;
            int r = idx >> 2, sg = idx & 3;
            uint32_t so = (uint32_t)(r * ROWB + sg * 16);
            cpa16(sb + so,       srcH + (size_t)r * MDIM + sg * 8);
            cpa16(sb + ASZ + so, srcL + (size_t)r * MDIM + sg * 8);
        }
#pragma unroll
        for (int i = 0; i < 4; i++) {            // B: 256 rows x 4 segs
            int idx = tid + i * 256;
            int r = idx >> 2, sg = idx & 3;
            cpa16(sb + 2 * ASZ + (uint32_t)(r * ROWB + sg * 16),
                  srcB + (size_t)r * MDIM + sg * 8);
        }
        CP_COMMIT();
    };

    auto compute = [&](int buf) {
        const uint32_t sb  = base + buf * STAGE;
        const uint32_t aH  = sb;
        const uint32_t aL  = sb + ASZ;
        const uint32_t bB  = sb + 2 * ASZ;
#pragma unroll
        for (int kk = 0; kk < 2; kk++) {
            const int kb = kk * 32;  // 16 bf16 = 32 bytes
            unsigned ah[4][4], al[4][4], bb[8][2];
#pragma unroll
            for (int mt = 0; mt < 4; mt++) {
                uint32_t ao = (uint32_t)((aRow + mt * 16) * ROWB + kb + aKh);
                ldm_x4(ah[mt], aH + ao);
                ldm_x4(al[mt], aL + ao);
            }
#pragma unroll
            for (int ntp = 0; ntp < 4; ntp++) {
                unsigned t[4];
                ldm_x4(t, bB + (uint32_t)((bRow + ntp * 16) * ROWB + kb + bKh));
                bb[2 * ntp][0] = t[0]; bb[2 * ntp][1] = t[1];
                bb[2 * ntp + 1][0] = t[2]; bb[2 * ntp + 1][1] = t[3];
            }
#pragma unroll
            for (int mt = 0; mt < 4; mt++)
#pragma unroll
                for (int nt = 0; nt < 8; nt++) {
                    mma16816(acc[mt][nt], ah[mt], bb[nt]);
                    mma16816(acc[mt][nt], al[mt], bb[nt]);
                }
        }
    };

    // ---- pipeline: 8 chunks, 2-stage ring ----
    load_chunk(0, 0);
#pragma unroll
    for (int kc = 0; kc < 8; kc++) {
        if (kc < 7) {
            load_chunk(kc + 1, (kc + 1) & 1);
            cp_wait<1>();
        } else {
            cp_wait<0>();
        }
        __syncthreads();
        compute(kc & 1);
        __syncthreads();
    }

    // ---- epilogue: scale, write raw scores, (max,sumexp) partials ----
#pragma unroll
    for (int mt = 0; mt < 4; mt++) {
#pragma unroll
        for (int nt = 0; nt < 8; nt++) {
            int cl = warp_n * 64 + nt * 8 + 2 * q;
            float s0 = sNorm[cl];
            float s1 = sNorm[cl + 1];
            acc[mt][nt][0] *= s0;
            acc[mt][nt][1] *= s1;
            acc[mt][nt][2] *= s0;
            acc[mt][nt][3] *= s1;
        }
#pragma unroll
        for (int h = 0; h < 2; h++) {
            int rloc = warp_m * 64 + mt * 16 + g + h * 8;
            size_t orow = (size_t)(row0 + rloc) * NKEYS + n0;
            float mymax = -3.0e38f;
#pragma unroll
            for (int nt = 0; nt < 8; nt++) {
                int cl = warp_n * 64 + nt * 8 + 2 * q;
                float v0 = acc[mt][nt][h * 2 + 0];
                float v1 = acc[mt][nt][h * 2 + 1];
                *reinterpret_cast<float2*>(out + orow + cl) = make_float2(v0, v1);
                mymax = fmaxf(mymax, fmaxf(v0, v1));
            }
            float s = 0.f;
#pragma unroll
            for (int nt = 0; nt < 8; nt++) {
                s += __expf(acc[mt][nt][h * 2 + 0] - mymax);
                s += __expf(acc[mt][nt][h * 2 + 1] - mymax);
            }
#pragma unroll
            for (int off = 1; off <= 2; off <<= 1) {
                float mo = __shfl_xor_sync(0xffffffffu, mymax, off);
                float so = __shfl_xor_sync(0xffffffffu, s, off);
                float nm = fmaxf(mymax, mo);
                s = s * __expf(mymax - nm) + so * __expf(mo - nm);
                mymax = nm;
            }
            if (q == 0) sRed[warp_n][rloc] = make_float2(mymax, s);
        }
    }
    __syncthreads();
    if (tid < 128) {
        float2 a = sRed[0][tid], b = sRed[1][tid];
        float2 c = sRed[2][tid], d = sRed[3][tid];
        float M = fmaxf(fmaxf(a.x, b.x), fmaxf(c.x, d.x));
        float S = a.y * __expf(a.x - M) + b.y * __expf(b.x - M) +
                  c.y * __expf(c.x - M) + d.y * __expf(d.x - M);
        size_t p = ((size_t)(row0 + tid) * CTILES + blockIdx.y) * 2;
        g_part[p]     = M;
        g_part[p + 1] = S;
    }
}

// ---------------------------------------------------------------
// K3: per-row log-sum-exp reduction of 128 partials (R4 verbatim)
// ---------------------------------------------------------------
__global__ void reduce_kernel() {
    int b = blockIdx.x, t = threadIdx.x;
    size_t base = ((size_t)b * CTILES + t) * 2;
    float m = g_part[base];
    float s = g_part[base + 1];
#pragma unroll
    for (int off = 16; off; off >>= 1) {
        float mo = __shfl_xor_sync(0xffffffffu, m, off);
        float so = __shfl_xor_sync(0xffffffffu, s, off);
        float nm = fmaxf(m, mo);
        s = s * __expf(m - nm) + so * __expf(mo - nm);
        m = nm;
    }
    __shared__ float sm[4], ss[4];
    if ((t & 31) == 0) { sm[t >> 5] = m; ss[t >> 5] = s; }
    __syncthreads();
    if (t < 32) {
        if (t < 4) { m = sm[t]; s = ss[t]; }
        else       { m = -3.0e38f; s = 0.f; }
#pragma unroll
        for (int off = 2; off; off >>= 1) {
            float mo = __shfl_xor_sync(0xffffffffu, m, off);
            float so = __shfl_xor_sync(0xffffffffu, s, off);
            float nm = fmaxf(m, mo);
            s = s * __expf(m - nm) + so * __expf(mo - nm);
            m = nm;
        }
        if (t == 0) g_rowstats[b] = make_float2(m, 1.0f / s);
    }
}

// ---------------------------------------------------------------
// K4: out = exp(score - M) * invS   (in-place over d_out, R4 verbatim)
// ---------------------------------------------------------------
__global__ void norm_kernel(float* __restrict__ out) {
    const size_t total4 = (size_t)BATCH * NKEYS / 4;
    size_t stride = (size_t)gridDim.x * blockDim.x;
    for (size_t i4 = (size_t)blockIdx.x * blockDim.x + threadIdx.x;
         i4 < total4; i4 += stride) {
        int b = (int)(i4 >> 13);  // 8192 float4 per row
        float2 st = __ldg(&g_rowstats[b]);
        float4 v = reinterpret_cast<float4*>(out)[i4];
        v.x = __expf(v.x - st.x) * st.y;
        v.y = __expf(v.y - st.x) * st.y;
        v.z = __expf(v.z - st.x) * st.y;
        v.w = __expf(v.w - st.x) * st.y;
        reinterpret_cast<float4*>(out)[i4] = v;
    }
}

// ---------------------------------------------------------------
extern "C" void kernel_launch(void* const* d_in, const int* in_sizes, int n_in,
                              void* d_out, int out_size) {
    const float* query  = (const float*)d_in[0];  // [2048, 128]
    const float* keys   = (const float*)d_in[1];  // [32768, 256] (+/-1)
    const float* norms  = (const float*)d_in[2];  // [32768]
    const float* sketch = (const float*)d_in[3];  // [256, 128]
    float* out = (float*)d_out;                   // [2048, 32768]

    cudaFuncSetAttribute(gemm_kernel, cudaFuncAttributeMaxDynamicSharedMemorySize, SMEM_DYN);

    convert_keys<<<(NKEYS * MDIM / 4) / 256, 256>>>(keys);
    project_kernel<<<BATCH / 8, 256>>>(query, sketch);
    dim3 g2(BATCH / 128, CTILES);  // m-fastest: slabs share key tiles in-wave
    gemm_kernel<<<g2, 256, SMEM_DYN>>>(norms, out);
    reduce_kernel<<<BATCH, 128>>>();
    norm_kernel<<<16384, 256>>>(out);
}

// round 11
// speedup vs baseline: 1.4794x; 1.0234x over previous
#include <cuda_runtime.h>
#include <cuda_bf16.h>
#include <cstdint>

#define BATCH 2048
#define DDIM  128
#define MDIM  256
#define NKEYS 32768
#define NTILE 256                  // keys per CTA tile
#define CTILES (NKEYS / NTILE)     // 128
#define EST_CONST 0.0048957583f    // float32(sqrt(pi/2)/256)

// -------- static device scratch (no allocations allowed) --------
__device__ __align__(16) __nv_bfloat16 g_Ahi[BATCH * MDIM];
__device__ __align__(16) __nv_bfloat16 g_Alo[BATCH * MDIM];
__device__ __align__(16) __nv_bfloat16 g_Kbf[(size_t)NKEYS * MDIM];
__device__ float  g_part[(size_t)BATCH * CTILES * 2];
__device__ float2 g_rowstats[BATCH];

// ---------------- PTX helpers (compute_103-safe) ----------------
__device__ __forceinline__ uint32_t smem_u32(const void* p) {
    uint32_t a;
    asm("{ .reg .u64 t; cvta.to.shared.u64 t, %1; cvt.u32.u64 %0, t; }" : "=r"(a) : "l"(p));
    return a;
}
__device__ __forceinline__ void cpa16(uint32_t dst, const void* src) {
    asm volatile("cp.async.cg.shared.global [%0], [%1], 16;" :: "r"(dst), "l"(src));
}
#define CP_COMMIT() asm volatile("cp.async.commit_group;" ::: "memory")
template <int N> __device__ __forceinline__ void cp_wait() {
    asm volatile("cp.async.wait_group %0;" :: "n"(N) : "memory");
}
__device__ __forceinline__ void ldm_x4(unsigned* r, uint32_t addr) {
    asm volatile("ldmatrix.sync.aligned.m8n8.x4.shared.b16 {%0,%1,%2,%3}, [%4];"
                 : "=r"(r[0]), "=r"(r[1]), "=r"(r[2]), "=r"(r[3]) : "r"(addr));
}
__device__ __forceinline__ void mma16816(float* c, const unsigned* a, const unsigned* b) {
    asm volatile(
        "mma.sync.aligned.m16n8k16.row.col.f32.bf16.bf16.f32 "
        "{%0,%1,%2,%3}, {%4,%5,%6,%7}, {%8,%9}, {%0,%1,%2,%3};\n"
        : "+f"(c[0]), "+f"(c[1]), "+f"(c[2]), "+f"(c[3])
        : "r"(a[0]), "r"(a[1]), "r"(a[2]), "r"(a[3]), "r"(b[0]), "r"(b[1]));
}

// ---------------------------------------------------------------
// K0: convert keys fp32 (+/-1) -> bf16 (exact). Standalone: low regs,
// full occupancy. __ldcs: single-use fp32 stream must not evict the
// bf16 key image from L2.
// ---------------------------------------------------------------
__global__ void convert_keys(const float* __restrict__ keys) {
    size_t i = (size_t)blockIdx.x * blockDim.x + threadIdx.x;  // one float4 each
    float4 v = __ldcs((const float4*)keys + i);
    __nv_bfloat162 a = __floats2bfloat162_rn(v.x, v.y);
    __nv_bfloat162 b = __floats2bfloat162_rn(v.z, v.w);
    ((__nv_bfloat162*)g_Kbf)[2 * i]     = a;
    ((__nv_bfloat162*)g_Kbf)[2 * i + 1] = b;
}

// ---------------------------------------------------------------
// K1: projection, 8 batch rows per CTA (sketch traffic 8x lower than
// one-row-per-CTA). PQ = query @ sketch^T -> bf16 hi/lo split.
// ---------------------------------------------------------------
__global__ void project_kernel(const float* __restrict__ query,
                               const float* __restrict__ sketch) {
    __shared__ float4 qs[8][DDIM / 4];
    const int b0 = blockIdx.x * 8;
    const int t  = threadIdx.x;          // 0..255
    qs[t >> 5][t & 31] = ((const float4*)(query + (size_t)b0 * DDIM))[t];
    __syncthreads();

    const int m = t;                      // 0..255
    const float4* skr = (const float4*)(sketch + (size_t)m * DDIM);
    float acc[8];
#pragma unroll
    for (int b = 0; b < 8; b++) acc[b] = 0.f;
#pragma unroll
    for (int i = 0; i < DDIM / 4; i++) {
        float4 s = skr[i];
#pragma unroll
        for (int b = 0; b < 8; b++) {
            float4 a = qs[b][i];          // smem broadcast (conflict-free)
            acc[b] += a.x * s.x + a.y * s.y + a.z * s.z + a.w * s.w;
        }
    }
#pragma unroll
    for (int b = 0; b < 8; b++) {
        __nv_bfloat16 hi = __float2bfloat16(acc[b]);
        float rem = acc[b] - __bfloat162float(hi);
        g_Ahi[(size_t)(b0 + b) * MDIM + m] = hi;
        g_Alo[(size_t)(b0 + b) * MDIM + m] = __float2bfloat16(rem);
    }
}

// ---------------------------------------------------------------
// K2: HMMA GEMM (R4/R10-proven, verbatim). CTA 128(M) x 256(N),
// K=256 in 8 chunks of 32, hi/lo folded, cp.async double buffer.
// 8 warps, warp tile 64x64. Rows padded to 80B (conflict-free).
// ---------------------------------------------------------------
#define ROWB 80                      // bytes per smem row (32 bf16 + pad)
#define ASZ  (128 * ROWB)            // 10240 B per A operand
#define BSZ  (256 * ROWB)            // 20480 B
#define STAGE (2 * ASZ + BSZ)        // 40960 B
#define SMEM_DYN (2 * STAGE)         // 81920 B

__global__ void __launch_bounds__(256, 1)
gemm_kernel(const float* __restrict__ norms, float* __restrict__ out) {
    extern __shared__ char dsm[];
    __shared__ float  sNorm[NTILE];
    __shared__ float2 sRed[4][128];

    const int tid  = threadIdx.x;
    const int wid  = tid >> 5;
    const int lane = tid & 31;
    const int warp_m = wid & 1;   // 2 over 128 rows (64 each)
    const int warp_n = wid >> 1;  // 4 over 256 cols (64 each)
    const int g = lane >> 2;
    const int q = lane & 3;
    const int row0 = blockIdx.x * 128;
    const int n0   = blockIdx.y * NTILE;

    const uint32_t base = smem_u32(dsm);

    for (int i = tid; i < NTILE; i += 256)
        sNorm[i] = __ldg(norms + n0 + i) * EST_CONST;

    float acc[4][8][4];
#pragma unroll
    for (int mt = 0; mt < 4; mt++)
#pragma unroll
        for (int nt = 0; nt < 8; nt++)
#pragma unroll
            for (int c = 0; c < 4; c++) acc[mt][nt][c] = 0.f;

    const int aRow = warp_m * 64 + (lane & 7) + ((lane >> 3) & 1) * 8;  // + mt*16
    const int aKh  = (lane >> 4) * 16;
    const int bRow = warp_n * 64 + (lane & 7) + ((lane >> 4) & 1) * 8;  // + ntp*16
    const int bKh  = ((lane >> 3) & 1) * 16;

    auto load_chunk = [&](int kc, int buf) {
        const uint32_t sb = base + buf * STAGE;
        const __nv_bfloat16* srcH = g_Ahi + (size_t)row0 * MDIM + kc * 32;
        const __nv_bfloat16* srcL = g_Alo + (size_t)row0 * MDIM + kc * 32;
        const __nv_bfloat16* srcB = g_Kbf + (size_t)n0 * MDIM + kc * 32;
#pragma unroll
        for (int i = 0; i < 2; i++) {            // A hi/lo: 128 rows x 4 segs
            int idx = tid + i * 256;
            int r = idx >> 2, sg = idx & 3;
            uint32_t so = (uint32_t)(r * ROWB + sg * 16);
            cpa16(sb + so,       srcH + (size_t)r * MDIM + sg * 8);
            cpa16(sb + ASZ + so, srcL + (size_t)r * MDIM + sg * 8);
        }
#pragma unroll
        for (int i = 0; i < 4; i++) {            // B: 256 rows x 4 segs
            int idx = tid + i * 256;
            int r = idx >> 2, sg = idx & 3;
            cpa16(sb + 2 * ASZ + (uint32_t)(r * ROWB + sg * 16),
                  srcB + (size_t)r * MDIM + sg * 8);
        }
        CP_COMMIT();
    };

    auto compute = [&](int buf) {
        const uint32_t sb  = base + buf * STAGE;
        const uint32_t aH  = sb;
        const uint32_t aL  = sb + ASZ;
        const uint32_t bB  = sb + 2 * ASZ;
#pragma unroll
        for (int kk = 0; kk < 2; kk++) {
            const int kb = kk * 32;  // 16 bf16 = 32 bytes
            unsigned ah[4][4], al[4][4], bb[8][2];
#pragma unroll
            for (int mt = 0; mt < 4; mt++) {
                uint32_t ao = (uint32_t)((aRow + mt * 16) * ROWB + kb + aKh);
                ldm_x4(ah[mt], aH + ao);
                ldm_x4(al[mt], aL + ao);
            }
#pragma unroll
            for (int ntp = 0; ntp < 4; ntp++) {
                unsigned t[4];
                ldm_x4(t, bB + (uint32_t)((bRow + ntp * 16) * ROWB + kb + bKh));
                bb[2 * ntp][0] = t[0]; bb[2 * ntp][1] = t[1];
                bb[2 * ntp + 1][0] = t[2]; bb[2 * ntp + 1][1] = t[3];
            }
#pragma unroll
            for (int mt = 0; mt < 4; mt++)
#pragma unroll
                for (int nt = 0; nt < 8; nt++) {
                    mma16816(acc[mt][nt], ah[mt], bb[nt]);
                    mma16816(acc[mt][nt], al[mt], bb[nt]);
                }
        }
    };

    // ---- pipeline: 8 chunks, 2-stage ring ----
    load_chunk(0, 0);
#pragma unroll
    for (int kc = 0; kc < 8; kc++) {
        if (kc < 7) {
            load_chunk(kc + 1, (kc + 1) & 1);
            cp_wait<1>();
        } else {
            cp_wait<0>();
        }
        __syncthreads();
        compute(kc & 1);
        __syncthreads();
    }

    // ---- epilogue: scale, write raw scores, (max,sumexp) partials ----
#pragma unroll
    for (int mt = 0; mt < 4; mt++) {
#pragma unroll
        for (int nt = 0; nt < 8; nt++) {
            int cl = warp_n * 64 + nt * 8 + 2 * q;
            float s0 = sNorm[cl];
            float s1 = sNorm[cl + 1];
            acc[mt][nt][0] *= s0;
            acc[mt][nt][1] *= s1;
            acc[mt][nt][2] *= s0;
            acc[mt][nt][3] *= s1;
        }
#pragma unroll
        for (int h = 0; h < 2; h++) {
            int rloc = warp_m * 64 + mt * 16 + g + h * 8;
            size_t orow = (size_t)(row0 + rloc) * NKEYS + n0;
            float mymax = -3.0e38f;
#pragma unroll
            for (int nt = 0; nt < 8; nt++) {
                int cl = warp_n * 64 + nt * 8 + 2 * q;
                float v0 = acc[mt][nt][h * 2 + 0];
                float v1 = acc[mt][nt][h * 2 + 1];
                *reinterpret_cast<float2*>(out + orow + cl) = make_float2(v0, v1);
                mymax = fmaxf(mymax, fmaxf(v0, v1));
            }
            float s = 0.f;
#pragma unroll
            for (int nt = 0; nt < 8; nt++) {
                s += __expf(acc[mt][nt][h * 2 + 0] - mymax);
                s += __expf(acc[mt][nt][h * 2 + 1] - mymax);
            }
#pragma unroll
            for (int off = 1; off <= 2; off <<= 1) {
                float mo = __shfl_xor_sync(0xffffffffu, mymax, off);
                float so = __shfl_xor_sync(0xffffffffu, s, off);
                float nm = fmaxf(mymax, mo);
                s = s * __expf(mymax - nm) + so * __expf(mo - nm);
                mymax = nm;
            }
            if (q == 0) sRed[warp_n][rloc] = make_float2(mymax, s);
        }
    }
    __syncthreads();
    if (tid < 128) {
        float2 a = sRed[0][tid], b = sRed[1][tid];
        float2 c = sRed[2][tid], d = sRed[3][tid];
        float M = fmaxf(fmaxf(a.x, b.x), fmaxf(c.x, d.x));
        float S = a.y * __expf(a.x - M) + b.y * __expf(b.x - M) +
                  c.y * __expf(c.x - M) + d.y * __expf(d.x - M);
        size_t p = ((size_t)(row0 + tid) * CTILES + blockIdx.y) * 2;
        g_part[p]     = M;
        g_part[p + 1] = S;
    }
}

// ---------------------------------------------------------------
// K3: per-row log-sum-exp reduction of 128 partials (R10 verbatim)
// ---------------------------------------------------------------
__global__ void reduce_kernel() {
    int b = blockIdx.x, t = threadIdx.x;
    size_t base = ((size_t)b * CTILES + t) * 2;
    float m = g_part[base];
    float s = g_part[base + 1];
#pragma unroll
    for (int off = 16; off; off >>= 1) {
        float mo = __shfl_xor_sync(0xffffffffu, m, off);
        float so = __shfl_xor_sync(0xffffffffu, s, off);
        float nm = fmaxf(m, mo);
        s = s * __expf(m - nm) + so * __expf(mo - nm);
        m = nm;
    }
    __shared__ float sm[4], ss[4];
    if ((t & 31) == 0) { sm[t >> 5] = m; ss[t >> 5] = s; }
    __syncthreads();
    if (t < 32) {
        if (t < 4) { m = sm[t]; s = ss[t]; }
        else       { m = -3.0e38f; s = 0.f; }
#pragma unroll
        for (int off = 2; off; off >>= 1) {
            float mo = __shfl_xor_sync(0xffffffffu, m, off);
            float so = __shfl_xor_sync(0xffffffffu, s, off);
            float nm = fmaxf(m, mo);
            s = s * __expf(m - nm) + so * __expf(mo - nm);
            m = nm;
        }
        if (t == 0) g_rowstats[b] = make_float2(m, 1.0f / s);
    }
}

// ---------------------------------------------------------------
// K4: out = exp(score - M) * invS, iterated CTILE-DESCENDING.
// The gemm's grid (slab=x fast, ctile=y slow) wrote high ctiles last,
// so L2 (~126MB) holds ctiles ~70..127 of all rows. Visiting ctile 127
// downward consumes the resident region as pure L2 hits BEFORE any
// cold-read eviction begins (hits don't allocate). ~110MB of DRAM
// reads become L2 hits.
// Grid 32768: bid>>8 = descending-ctile index, bid&255 = 8-row group.
// Thread: rows t>>5 (8 rows/CTA), two float4 per row (MLP=2).
// ---------------------------------------------------------------
__global__ void __launch_bounds__(256)
norm_kernel(float* __restrict__ out) {
    const int ctile = (CTILES - 1) - (blockIdx.x >> 8);   // 127 -> 0
    const int rg    = blockIdx.x & 255;                   // 256 groups of 8 rows
    const int t     = threadIdx.x;
    const int row   = rg * 8 + (t >> 5);
    const int c4    = t & 31;                             // float4 idx in tile

    const float2 st = __ldg(&g_rowstats[row]);
    float4* p = (float4*)(out + (size_t)row * NKEYS + ctile * NTILE);
    float4 v0 = p[c4];
    float4 v1 = p[c4 + 32];
    v0.x = __expf(v0.x - st.x) * st.y;
    v0.y = __expf(v0.y - st.x) * st.y;
    v0.z = __expf(v0.z - st.x) * st.y;
    v0.w = __expf(v0.w - st.x) * st.y;
    v1.x = __expf(v1.x - st.x) * st.y;
    v1.y = __expf(v1.y - st.x) * st.y;
    v1.z = __expf(v1.z - st.x) * st.y;
    v1.w = __expf(v1.w - st.x) * st.y;
    p[c4]      = v0;
    p[c4 + 32] = v1;
}

// ---------------------------------------------------------------
extern "C" void kernel_launch(void* const* d_in, const int* in_sizes, int n_in,
                              void* d_out, int out_size) {
    const float* query  = (const float*)d_in[0];  // [2048, 128]
    const float* keys   = (const float*)d_in[1];  // [32768, 256] (+/-1)
    const float* norms  = (const float*)d_in[2];  // [32768]
    const float* sketch = (const float*)d_in[3];  // [256, 128]
    float* out = (float*)d_out;                   // [2048, 32768]

    cudaFuncSetAttribute(gemm_kernel, cudaFuncAttributeMaxDynamicSharedMemorySize, SMEM_DYN);

    convert_keys<<<(NKEYS * MDIM / 4) / 256, 256>>>(keys);
    project_kernel<<<BATCH / 8, 256>>>(query, sketch);
    dim3 g2(BATCH / 128, CTILES);  // m-fastest: slabs share key tiles in-wave
    gemm_kernel<<<g2, 256, SMEM_DYN>>>(norms, out);
    reduce_kernel<<<BATCH, 128>>>();
    norm_kernel<<<CTILES * 256, 256>>>(out);
}